// round 17
// baseline (speedup 1.0000x reference)
#include <cuda_runtime.h>
#include <cuda_bf16.h>
#include <cuda_fp16.h>
#include <cstdint>

#define NCTX 4096
#define DM   512
#define NB   2
#define LDKT (NB*NCTX)

// Scratch
__device__ __nv_bfloat16 g_xhi[(size_t)NB*NCTX*DM];
__device__ __nv_bfloat16 g_xlo[(size_t)NB*NCTX*DM];
__device__ __nv_bfloat16 g_Whi[(size_t)DM*DM];
__device__ __nv_bfloat16 g_Wlo[(size_t)DM*DM];
__device__ __nv_bfloat16 g_Khi[(size_t)NB*NCTX*DM];
__device__ __nv_bfloat16 g_Klo[(size_t)NB*NCTX*DM];
__device__ __half        g_Ktb[(size_t)DM*NB*NCTX];   // fp16 K^T
__device__ float         g_S  [(size_t)NB*NCTX*NCTX]; // fp32 scores
__device__ __half        g_Pb [(size_t)NB*NCTX*NCTX]; // fp16 exp(s-m)
__device__ float         g_inv[(size_t)NB*NCTX];      // 1 / rowsum(exp)

// ---------------------------------------------------------------------------
// helpers
// ---------------------------------------------------------------------------
__device__ __forceinline__ uint32_t s2u(const void* p){
  uint32_t a;
  asm("{ .reg .u64 t; cvta.to.shared.u64 t, %1; cvt.u32.u64 %0, t; }" : "=r"(a) : "l"(p));
  return a;
}
__device__ __forceinline__ void ldsm4(uint32_t* r, uint32_t addr){
  asm volatile("ldmatrix.sync.aligned.m8n8.x4.shared.b16 {%0,%1,%2,%3}, [%4];"
    : "=r"(r[0]), "=r"(r[1]), "=r"(r[2]), "=r"(r[3]) : "r"(addr));
}
__device__ __forceinline__ void bmma(float* c, const uint32_t* a, const uint32_t* b){
  asm volatile("mma.sync.aligned.m16n8k16.row.col.f32.bf16.bf16.f32 "
    "{%0,%1,%2,%3}, {%4,%5,%6,%7}, {%8,%9}, {%0,%1,%2,%3};"
    : "+f"(c[0]), "+f"(c[1]), "+f"(c[2]), "+f"(c[3])
    : "r"(a[0]), "r"(a[1]), "r"(a[2]), "r"(a[3]), "r"(b[0]), "r"(b[1]));
}
__device__ __forceinline__ void hmma(float* c, const uint32_t* a, const uint32_t* b){
  asm volatile("mma.sync.aligned.m16n8k16.row.col.f32.f16.f16.f32 "
    "{%0,%1,%2,%3}, {%4,%5,%6,%7}, {%8,%9}, {%0,%1,%2,%3};"
    : "+f"(c[0]), "+f"(c[1]), "+f"(c[2]), "+f"(c[3])
    : "r"(a[0]), "r"(a[1]), "r"(a[2]), "r"(a[3]), "r"(b[0]), "r"(b[1]));
}
__device__ __forceinline__ void cp16(uint32_t d, const void* s){
  asm volatile("cp.async.cg.shared.global [%0], [%1], 16;" :: "r"(d), "l"(s));
}
__device__ __forceinline__ void cp_commit(){
  asm volatile("cp.async.commit_group;" ::: "memory");
}
template<int N> __device__ __forceinline__ void cp_wait(){
  asm volatile("cp.async.wait_group %0;" :: "n"(N) : "memory");
}

// ===========================================================================
// bf16 split (3-MMA) GEMM, 512 threads: C[128 x 256] = A * B^T (hi/lo).
// BK=32, 3 stages, pitch 80 B. 16 warps = 4(M) x 4(N); warp tile 32x64.
// Term-major inner ordering (accumulator reuse distance 8).
// ===========================================================================
#define A_TILE5 10240                       // 128 * 80
#define B_TILE5 20480                       // 256 * 80
#define STAGE5  (2*A_TILE5 + 2*B_TILE5)     // 61440; 3 stages = 184320

template<class EPI>
__device__ __forceinline__ void bgemm512(
    const __nv_bfloat16* __restrict__ Ah, const __nv_bfloat16* __restrict__ Al, int lda,
    const __nv_bfloat16* __restrict__ Bh, const __nv_bfloat16* __restrict__ Bl, int ldb,
    int m0, int n0, int k1, EPI&& epi)
{
  extern __shared__ __align__(16) char sd[];
  const int t = threadIdx.x, l = t & 31, w = t >> 5;
  const int wm = w & 3, wn = w >> 2;
  const uint32_t sb = s2u(sd);

  const int arow = t >> 2, aseg = (t & 3) * 8;
  const uint32_t soA = (uint32_t)arow*80 + (t & 3)*16;
  const __nv_bfloat16* pAh = Ah + (size_t)(m0 + arow)*lda + aseg;
  const __nv_bfloat16* pAl = Al + (size_t)(m0 + arow)*lda + aseg;
  const __nv_bfloat16* pBh = Bh + (size_t)(n0 + arow)*ldb + aseg;
  const __nv_bfloat16* pBl = Bl + (size_t)(n0 + arow)*ldb + aseg;
  const __nv_bfloat16* qBh = Bh + (size_t)(n0 + arow + 128)*ldb + aseg;
  const __nv_bfloat16* qBl = Bl + (size_t)(n0 + arow + 128)*ldb + aseg;
  const uint32_t soB2 = soA + 128*80;

  const int nch = k1 >> 5;
  auto load_stage = [&](int c){
    const int kb = c << 5;
    const uint32_t st = sb + (c % 3)*STAGE5;
    cp16(st + soA,                        pAh + kb);
    cp16(st + soA + A_TILE5,              pAl + kb);
    cp16(st + soA + 2*A_TILE5,            pBh + kb);
    cp16(st + soB2 + 2*A_TILE5,           qBh + kb);
    cp16(st + soA + 2*A_TILE5 + B_TILE5,  pBl + kb);
    cp16(st + soB2 + 2*A_TILE5 + B_TILE5, qBl + kb);
  };
  load_stage(0); cp_commit();
  if (nch > 1) load_stage(1);
  cp_commit();

  const uint32_t aoff = (uint32_t)(wm*32 + (l & 15))*80 + ((l >> 4) & 1)*16;
  const uint32_t boff = (uint32_t)(wn*64 + (l & 7) + ((l >> 4) & 1)*8)*80
                      + ((l >> 3) & 1)*16;

  float acc[2][8][4] = {};

  for (int c = 0; c < nch; c++){
    cp_wait<1>();
    __syncthreads();
    if (c + 2 < nch) load_stage(c + 2);
    cp_commit();

    const uint32_t base = sb + (c % 3)*STAGE5;
    const uint32_t uAh = base + aoff,               uAl = uAh + A_TILE5;
    const uint32_t uBh = base + 2*A_TILE5 + boff,   uBl = uBh + B_TILE5;

    #pragma unroll
    for (int kf = 0; kf < 2; kf++){
      const uint32_t ko = kf*32;
      uint32_t ah[2][4], al[2][4];
      ldsm4(ah[0], uAh + ko);  ldsm4(ah[1], uAh + ko + 16*80);
      ldsm4(al[0], uAl + ko);  ldsm4(al[1], uAl + ko + 16*80);
      #pragma unroll
      for (int h = 0; h < 2; h++){
        uint32_t bh[2][4], bl[2][4];
        ldsm4(bh[0], uBh + ko + (2*h    )*16*80);
        ldsm4(bh[1], uBh + ko + (2*h + 1)*16*80);
        ldsm4(bl[0], uBl + ko + (2*h    )*16*80);
        ldsm4(bl[1], uBl + ko + (2*h + 1)*16*80);
        #pragma unroll
        for (int j = 0; j < 2; j++)
          #pragma unroll
          for (int mf = 0; mf < 2; mf++){
            bmma(acc[mf][2*(2*h+j)],     ah[mf], bh[j]);
            bmma(acc[mf][2*(2*h+j) + 1], ah[mf], bh[j] + 2);
          }
        #pragma unroll
        for (int j = 0; j < 2; j++)
          #pragma unroll
          for (int mf = 0; mf < 2; mf++){
            bmma(acc[mf][2*(2*h+j)],     ah[mf], bl[j]);
            bmma(acc[mf][2*(2*h+j) + 1], ah[mf], bl[j] + 2);
          }
        #pragma unroll
        for (int j = 0; j < 2; j++)
          #pragma unroll
          for (int mf = 0; mf < 2; mf++){
            bmma(acc[mf][2*(2*h+j)],     al[mf], bh[j]);
            bmma(acc[mf][2*(2*h+j) + 1], al[mf], bh[j] + 2);
          }
      }
    }
  }
  epi(acc);
}

// store epilogue for 512-thread gemm
__device__ __forceinline__ void epi_store5(float (&acc)[2][8][4],
                                           float* __restrict__ C, int ldc,
                                           int m0, int n0)
{
  const int t = threadIdx.x, l = t & 31, w = t >> 5;
  const int wm = w & 3, wn = w >> 2;
  #pragma unroll
  for (int mf = 0; mf < 2; mf++){
    const int r0 = m0 + wm*32 + mf*16 + (l >> 2);
    #pragma unroll
    for (int nf = 0; nf < 8; nf++){
      const int cc = n0 + wn*64 + nf*8 + 2*(l & 3);
      *(float2*)&C[(size_t)r0*ldc + cc]     = make_float2(acc[mf][nf][0], acc[mf][nf][1]);
      *(float2*)&C[(size_t)(r0+8)*ldc + cc] = make_float2(acc[mf][nf][2], acc[mf][nf][3]);
    }
  }
}

// ===========================================================================
// fp16 single GEMM, 256 threads: C[64 x 128] = A * B^T. BK=32, 3 stages.
// ===========================================================================
#define KA_T 5120
#define KB_T 10240
#define KST  (KA_T + KB_T)          // 15360; 3 stages = 46080

template<class EPI>
__device__ __forceinline__ void hgemm_out(
    const __half* __restrict__ A, int lda,
    const __half* __restrict__ B, int ldb,
    int m0, int n0, int k1, EPI&& epi)
{
  extern __shared__ __align__(16) char sd[];
  const int t = threadIdx.x, l = t & 31, w = t >> 5;
  const int wm = w & 1, wn = w >> 1;
  const uint32_t sb = s2u(sd);

  const int ar = t >> 2, as = (t & 3) * 8;
  const uint32_t soA = (uint32_t)ar*80 + (t & 3)*16;
  const __half* pA = A + (size_t)(m0 + ar)*lda + as;
  const __half* pB = B + (size_t)(n0 + ar)*ldb + as;

  cp_wait<0>();
  __syncthreads();

  const int nch = k1 >> 5;
  auto load_stage = [&](int c){
    const int kb = c << 5;
    const uint32_t st = sb + (c % 3)*KST;
    cp16(st + soA, pA + kb);
    cp16(st + KA_T + soA,        pB + kb);
    cp16(st + KA_T + soA + KA_T, pB + (size_t)64*ldb + kb);
  };
  load_stage(0); cp_commit();
  if (1 < nch) load_stage(1);
  cp_commit();

  const uint32_t aoff = (uint32_t)(wm*32 + (l & 15))*80 + ((l >> 4) & 1)*16;
  const uint32_t boff = (uint32_t)(wn*32 + (l & 7) + ((l >> 4) & 1)*8)*80
                      + ((l >> 3) & 1)*16;

  float acc[2][4][4] = {};

  for (int c = 0; c < nch; c++){
    cp_wait<1>();
    __syncthreads();
    if (c + 2 < nch) load_stage(c + 2);
    cp_commit();

    const uint32_t base = sb + (c % 3)*KST;
    const uint32_t uA = base + aoff;
    const uint32_t uB = base + KA_T + boff;

    #pragma unroll
    for (int kf = 0; kf < 2; kf++){
      const uint32_t ko = kf*32;
      uint32_t a[2][4];
      ldsm4(a[0], uA + ko);
      ldsm4(a[1], uA + ko + 16*80);
      #pragma unroll
      for (int nf2 = 0; nf2 < 2; nf2++){
        uint32_t b[4];
        ldsm4(b, uB + ko + nf2*16*80);
        #pragma unroll
        for (int mf = 0; mf < 2; mf++){
          hmma(acc[mf][2*nf2],     a[mf], b);
          hmma(acc[mf][2*nf2 + 1], a[mf], b + 2);
        }
      }
    }
  }
  epi(acc);
}

// ---------------------------------------------------------------------------
// Kernels
// ---------------------------------------------------------------------------
__global__ void __launch_bounds__(256)
k_prep(const float* __restrict__ x, const float* __restrict__ W)
{
  const size_t nx = (size_t)NB*NCTX*DM/4, nw = (size_t)DM*DM/4;
  for (size_t i = blockIdx.x*256 + threadIdx.x; i < nx + nw; i += (size_t)gridDim.x*256){
    float4 v;
    __nv_bfloat16* hi; __nv_bfloat16* lo; size_t j;
    if (i < nx){ v = ((const float4*)x)[i];      hi = g_xhi; lo = g_xlo; j = i; }
    else       { v = ((const float4*)W)[i - nx]; hi = g_Whi; lo = g_Wlo; j = i - nx; }
    __nv_bfloat16 hx = __float2bfloat16_rn(v.x), hy = __float2bfloat16_rn(v.y);
    __nv_bfloat16 hz = __float2bfloat16_rn(v.z), hw = __float2bfloat16_rn(v.w);
    __nv_bfloat162 h01; h01.x = hx; h01.y = hy;
    __nv_bfloat162 h23; h23.x = hz; h23.y = hw;
    __nv_bfloat162 l01; l01.x = __float2bfloat16_rn(v.x - __bfloat162float(hx));
                        l01.y = __float2bfloat16_rn(v.y - __bfloat162float(hy));
    __nv_bfloat162 l23; l23.x = __float2bfloat16_rn(v.z - __bfloat162float(hz));
                        l23.y = __float2bfloat16_rn(v.w - __bfloat162float(hw));
    ((__nv_bfloat162*)hi)[2*j]     = h01;
    ((__nv_bfloat162*)hi)[2*j + 1] = h23;
    ((__nv_bfloat162*)lo)[2*j]     = l01;
    ((__nv_bfloat162*)lo)[2*j + 1] = l23;
  }
}

__global__ void __launch_bounds__(512, 1)
k_proj()
{ // K = x @ W^T -> Khi/Klo (bf16, K-major) and g_Ktb (fp16, transposed)
  const int n0 = blockIdx.x*256, m0 = blockIdx.y*128;
  bgemm512(g_xhi, g_xlo, DM, g_Whi, g_Wlo, DM, m0, n0, DM,
    [&](float (&acc)[2][8][4]){
      const int t = threadIdx.x, l = t & 31, w = t >> 5;
      const int wm = w & 3, wn = w >> 2;
      #pragma unroll
      for (int mf = 0; mf < 2; mf++){
        const int r0 = m0 + wm*32 + mf*16 + (l >> 2);
        #pragma unroll
        for (int nf = 0; nf < 8; nf++){
          const int cc = n0 + wn*64 + nf*8 + 2*(l & 3);
          #pragma unroll
          for (int hh = 0; hh < 2; hh++){
            const int r = r0 + hh*8;
            const float v0 = acc[mf][nf][2*hh], v1 = acc[mf][nf][2*hh+1];
            __nv_bfloat16 h0 = __float2bfloat16_rn(v0), h1 = __float2bfloat16_rn(v1);
            __nv_bfloat162 hp; hp.x = h0; hp.y = h1;
            __nv_bfloat162 lp;
            lp.x = __float2bfloat16_rn(v0 - __bfloat162float(h0));
            lp.y = __float2bfloat16_rn(v1 - __bfloat162float(h1));
            const size_t ki = (size_t)r*DM + cc;
            *(__nv_bfloat162*)&g_Khi[ki] = hp;
            *(__nv_bfloat162*)&g_Klo[ki] = lp;
            g_Ktb[(size_t)cc    *LDKT + r] = __float2half_rn(v0);
            g_Ktb[(size_t)(cc+1)*LDKT + r] = __float2half_rn(v1);
          }
        }
      }
    });
}

__global__ void __launch_bounds__(512, 1)
k_scores()
{ // S = x @ K^T, lower-triangular 128x256 tiles (tile needed iff 2j <= i)
  const int b = blockIdx.z;
  const int j = blockIdx.x, i = blockIdx.y;
  if (2*j > i) return;
  const int n0 = j*256, m0 = i*128;
  const size_t off = (size_t)b*NCTX*DM;
  float* Sb = g_S + (size_t)b*NCTX*NCTX;
  bgemm512(g_xhi + off, g_xlo + off, DM, g_Khi + off, g_Klo + off, DM,
    m0, n0, DM,
    [&](float (&acc)[2][8][4]){ epi_store5(acc, Sb, NCTX, m0, n0); });
}

// ---------------------------------------------------------------------------
// softmax: paired rows (q, NCTX-1-q) per CTA -> every CTA sees 4097 elements.
// Row held in registers (single global read). Writes fp16 exp(s-m);
// g_inv = 1/rowsum; zero-fills P to 128 boundary.
// ---------------------------------------------------------------------------
__device__ __forceinline__ float blk_red(float v, bool is_max)
{
  __shared__ float sm[8];
  const int lane = threadIdx.x & 31, w = threadIdx.x >> 5;
  #pragma unroll
  for (int o = 16; o; o >>= 1){
    float u = __shfl_xor_sync(0xffffffffu, v, o);
    v = is_max ? fmaxf(v, u) : v + u;
  }
  if (lane == 0) sm[w] = v;
  __syncthreads();
  float r = sm[0];
  #pragma unroll
  for (int i = 1; i < 8; i++) r = is_max ? fmaxf(r, sm[i]) : r + sm[i];
  __syncthreads();
  return r;
}

__device__ __forceinline__ void softmax_row(int row, int q)
{
  const float* p = g_S + (size_t)row * NCTX;
  __half* pb = g_Pb + (size_t)row * NCTX;
  const int len  = q + 1;
  const int len4 = len >> 2;
  const float4* p4 = (const float4*)p;
  __half2* pb2 = (__half2*)pb;

  float4 v[4];
  float tl = 0.f;
  const int tidx = (len4 << 2) + threadIdx.x;
  const bool has_tail = (tidx < len);

  float m = -1e30f;
  #pragma unroll
  for (int k = 0; k < 4; k++){
    const int idx = threadIdx.x + (k << 8);
    if (idx < len4){
      v[k] = p4[idx];
      m = fmaxf(m, fmaxf(fmaxf(v[k].x, v[k].y), fmaxf(v[k].z, v[k].w)));
    }
  }
  if (has_tail){ tl = p[tidx]; m = fmaxf(m, tl); }
  m = blk_red(m, true);

  float s = 0.f;
  #pragma unroll
  for (int k = 0; k < 4; k++){
    const int idx = threadIdx.x + (k << 8);
    if (idx < len4){
      float ex = __expf(v[k].x - m), ey = __expf(v[k].y - m);
      float ez = __expf(v[k].z - m), ew = __expf(v[k].w - m);
      s += (ex + ey) + (ez + ew);
      pb2[2*idx]     = __floats2half2_rn(ex, ey);
      pb2[2*idx + 1] = __floats2half2_rn(ez, ew);
    }
  }
  if (has_tail){
    float e = __expf(tl - m);
    s += e;
    pb[tidx] = __float2half_rn(e);
  }
  s = blk_red(s, false);
  if (threadIdx.x == 0) g_inv[row] = 1.f / s;

  const int lenUp = (len + 127) & ~127;
  for (int i = len + threadIdx.x; i < lenUp; i += 256)
    pb[i] = __float2half_rn(0.f);
  __syncthreads();   // sm[] reuse across the two rows
}

__global__ void __launch_bounds__(256)
k_softmax()
{
  const int q = blockIdx.x;              // 0..2047
  const int b = blockIdx.y;
  softmax_row(b*NCTX + q,            q);
  softmax_row(b*NCTX + (NCTX-1-q), NCTX-1-q);
}

// ---------------------------------------------------------------------------
// out = x + (P @ K) * inv. fp16 single MMA. M_TILE=64, N_TILE=128.
// 256 equal CTAs: pair (i, 63-i) x 4 n-strips. No atomics.
// ---------------------------------------------------------------------------
__global__ void __launch_bounds__(256, 2)
k_out_h(const float* __restrict__ x, float* __restrict__ out)
{
  const int b    = blockIdx.z;
  const int n0   = blockIdx.x*128;
  const int pair = blockIdx.y;
  const __half* Pb = g_Pb  + (size_t)b*NCTX*NCTX;
  const __half* Bt = g_Ktb + (size_t)b*NCTX;

  #pragma unroll
  for (int s = 0; s < 2; s++){
    const int i  = s ? (63 - pair) : pair;
    const int m0 = i*64;
    hgemm_out(Pb, NCTX, Bt, LDKT, m0, n0, (i + 1)*64,
      [&](float (&acc)[2][4][4]){
        const int t = threadIdx.x, l = t & 31, w = t >> 5;
        const int wm = w & 1, wn = w >> 1;
        #pragma unroll
        for (int mf = 0; mf < 2; mf++){
          const int r0 = m0 + wm*32 + mf*16 + (l >> 2);
          const float inv0 = g_inv[b*NCTX + r0];
          const float inv1 = g_inv[b*NCTX + r0 + 8];
          #pragma unroll
          for (int nf = 0; nf < 4; nf++){
            const int cc = n0 + wn*32 + nf*8 + 2*(l & 3);
            const size_t i0 = (size_t)b*NCTX*DM + (size_t)r0*DM + cc;
            const size_t i1 = i0 + (size_t)8*DM;
            *(float2*)&out[i0] = make_float2(acc[mf][nf][0]*inv0 + x[i0],
                                             acc[mf][nf][1]*inv0 + x[i0+1]);
            *(float2*)&out[i1] = make_float2(acc[mf][nf][2]*inv1 + x[i1],
                                             acc[mf][nf][3]*inv1 + x[i1+1]);
          }
        }
      });
  }
}

// ---------------------------------------------------------------------------
extern "C" void kernel_launch(void* const* d_in, const int* in_sizes, int n_in,
                              void* d_out, int out_size)
{
  const float* x = (const float*)d_in[0];
  const float* W = (const float*)d_in[1];
  float* out = (float*)d_out;

  const int SMEM5    = 3 * STAGE5;     // 184320
  const int SMEM_OUT = 3 * KST;        // 46080
  cudaFuncSetAttribute(k_proj,   cudaFuncAttributeMaxDynamicSharedMemorySize, SMEM5);
  cudaFuncSetAttribute(k_scores, cudaFuncAttributeMaxDynamicSharedMemorySize, SMEM5);
  cudaFuncSetAttribute(k_out_h,  cudaFuncAttributeMaxDynamicSharedMemorySize, SMEM_OUT);

  k_prep   <<<1184, 256>>>(x, W);
  k_proj   <<<dim3(2, 64),       512, SMEM5>>>();
  k_scores <<<dim3(16, 32, NB),  512, SMEM5>>>();
  k_softmax<<<dim3(NCTX/2, NB),  256>>>();
  k_out_h  <<<dim3(4, 32, NB),   256, SMEM_OUT>>>(x, out);
}